// round 3
// baseline (speedup 1.0000x reference)
#include <cuda_runtime.h>
#include <math.h>

#define NSLICE 16
#define LSEQ   2048
#define DLLM   768
#define EDIM   64
#define EPS    1e-5f

#define QTILE  128          // query rows per CTA
#define KTILE  128          // keys per inner tile
#define NQT    (LSEQ/QTILE) // 16
#define PP     132          // P smem row pitch (pad for bank spread)

__device__ float g_q[NSLICE * LSEQ * EDIM];
__device__ float g_k[NSLICE * LSEQ * EDIM];
__device__ float g_v[NSLICE * LSEQ * EDIM];
__device__ float g_o[NSLICE * LSEQ * EDIM];
__device__ float2 g_part[NSLICE * NQT];
__device__ float2 g_stats[NSLICE];

// ----------------------------------------------------------------------------
// Fused projection: q,k,v = info @ {Wq,Wk,Wv} + {bq,bk,bv}
// Tile 128 rows x (3 x 64) cols, BK=32, 256 threads, frag 8 x (3x4).
// ----------------------------------------------------------------------------
__global__ __launch_bounds__(256, 1)
void proj_fused_kernel(const float* __restrict__ X,
                       const float* __restrict__ Wq, const float* __restrict__ bq,
                       const float* __restrict__ Wk, const float* __restrict__ bk,
                       const float* __restrict__ Wv, const float* __restrict__ bv)
{
    __shared__ float As[128 * 33];      // [row][k] pitch 33 -> conflict-free
    __shared__ float Bs[3 * 32 * 64];   // [w][k][col]

    const int s    = blockIdx.y;
    const int row0 = blockIdx.x * 128;
    const int tx = threadIdx.x & 15;
    const int ty = threadIdx.x >> 4;
    const int tid = threadIdx.x;

    const float* Xs = X + (size_t)s * LSEQ * DLLM + (size_t)row0 * DLLM;
    const float* Wp[3] = {Wq, Wk, Wv};

    float acc[3][8][4];
    #pragma unroll
    for (int w = 0; w < 3; ++w)
        #pragma unroll
        for (int i = 0; i < 8; ++i)
            #pragma unroll
            for (int j = 0; j < 4; ++j) acc[w][i][j] = 0.f;

    for (int k0 = 0; k0 < DLLM; k0 += 32) {
        // A tile: 128 rows x 32 k. 1024 float4 loads, scatter to pitch-33 rows.
        #pragma unroll
        for (int t = 0; t < 4; ++t) {
            int f = tid + t * 256;            // 0..1023
            int r  = f >> 3;
            int kc = (f & 7) * 4;
            float4 v4 = *reinterpret_cast<const float4*>(&Xs[(size_t)r * DLLM + k0 + kc]);
            float* dst = &As[r * 33 + kc];
            dst[0] = v4.x; dst[1] = v4.y; dst[2] = v4.z; dst[3] = v4.w;
        }
        // B tiles: 3 x 32 x 64
        #pragma unroll
        for (int t = 0; t < 6; ++t) {
            int f = tid + t * 256;            // 0..1535 float4s
            int w   = f >> 9;                 // 512 float4 per weight
            int rem = f & 511;
            int kk  = rem >> 4;
            int c   = (rem & 15) * 4;
            *reinterpret_cast<float4*>(&Bs[w * 2048 + kk * 64 + c]) =
                *reinterpret_cast<const float4*>(&Wp[w][(size_t)(k0 + kk) * EDIM + c]);
        }
        __syncthreads();

        #pragma unroll 4
        for (int kk = 0; kk < 32; ++kk) {
            float a[8];
            #pragma unroll
            for (int i = 0; i < 8; ++i) a[i] = As[(ty * 8 + i) * 33 + kk];
            #pragma unroll
            for (int w = 0; w < 3; ++w) {
                float4 b4 = *reinterpret_cast<const float4*>(&Bs[w * 2048 + kk * 64 + tx * 4]);
                #pragma unroll
                for (int i = 0; i < 8; ++i) {
                    acc[w][i][0] += a[i] * b4.x;
                    acc[w][i][1] += a[i] * b4.y;
                    acc[w][i][2] += a[i] * b4.z;
                    acc[w][i][3] += a[i] * b4.w;
                }
            }
        }
        __syncthreads();
    }

    const float* bp[3] = {bq, bk, bv};
    float* Yp[3] = {g_q, g_k, g_v};
    #pragma unroll
    for (int w = 0; w < 3; ++w) {
        float4 bb = *reinterpret_cast<const float4*>(&bp[w][tx * 4]);
        float* Ys = Yp[w] + (size_t)s * LSEQ * EDIM + (size_t)row0 * EDIM;
        #pragma unroll
        for (int i = 0; i < 8; ++i) {
            float4 r4;
            r4.x = acc[w][i][0] + bb.x;
            r4.y = acc[w][i][1] + bb.y;
            r4.z = acc[w][i][2] + bb.z;
            r4.w = acc[w][i][3] + bb.w;
            *reinterpret_cast<float4*>(&Ys[(size_t)(ty * 8 + i) * EDIM + tx * 4]) = r4;
        }
    }
}

// ----------------------------------------------------------------------------
// Flash attention: 128 query rows/CTA, 128-key tiles, 256 threads.
// QK phase: (ty,tx) in 16x16 owns an 8x8 S fragment (1.0 B/FMA).
// PV phase: (ry,re) = (tid/8, tid%8) owns 4 rows x 8 E cols (1.5 B/FMA).
// Softmax state per row lives in SMEM (row_m/row_l/row_alpha).
// ----------------------------------------------------------------------------
__global__ __launch_bounds__(256, 1)
void attn_kernel()
{
    extern __shared__ float sm[];
    float* Qs = sm;                       // 128*64
    float* Ks = Qs + 128 * 64;            // 128*64, e-swizzled
    float* Vs = Ks + 128 * 64;            // 128*64
    float* Ps = Vs + 128 * 64;            // 128*PP
    float* row_m     = Ps + 128 * PP;     // 128
    float* row_l     = row_m + 128;       // 128
    float* row_alpha = row_l + 128;       // 128

    const int s    = blockIdx.y;
    const int row0 = blockIdx.x * QTILE;
    const int tid = threadIdx.x;
    const int tx = tid & 15, ty = tid >> 4;     // QK mapping
    const int re = tid & 7,  ry = tid >> 3;     // PV mapping

    const float* Qg = g_q + (size_t)s * LSEQ * EDIM + (size_t)row0 * EDIM;
    const float* Kg = g_k + (size_t)s * LSEQ * EDIM;
    const float* Vg = g_v + (size_t)s * LSEQ * EDIM;

    // Load Q tile (row-major), init softmax state
    #pragma unroll
    for (int t = 0; t < 8; ++t) {
        int f = tid + t * 256;            // 2048 float4s
        int r = f >> 4, c = (f & 15) * 4;
        *reinterpret_cast<float4*>(&Qs[r * 64 + c]) =
            *reinterpret_cast<const float4*>(&Qg[(size_t)r * EDIM + c]);
    }
    if (tid < 128) { row_m[tid] = -1e30f; row_l[tid] = 0.f; }

    float O[4][8];
    #pragma unroll
    for (int i = 0; i < 4; ++i)
        #pragma unroll
        for (int j = 0; j < 8; ++j) O[i][j] = 0.f;

    const float scale = 0.125f;
    const int kswz = (tx & 7) << 2;       // read-side K swizzle for this thread

    for (int kt = 0; kt < LSEQ / KTILE; ++kt) {
        __syncthreads();  // previous PV reads of Vs/Ps done

        // Load K (e-swizzled) and V tiles
        #pragma unroll
        for (int t = 0; t < 8; ++t) {
            int f = tid + t * 256;
            int r = f >> 4, c = (f & 15) * 4;
            float4 kv4 = *reinterpret_cast<const float4*>(&Kg[(size_t)(kt * KTILE + r) * EDIM + c]);
            int cs = c ^ (((r >> 3) & 7) << 2);
            *reinterpret_cast<float4*>(&Ks[r * 64 + cs]) = kv4;
            *reinterpret_cast<float4*>(&Vs[r * 64 + c]) =
                *reinterpret_cast<const float4*>(&Vg[(size_t)(kt * KTILE + r) * EDIM + c]);
        }
        __syncthreads();

        // ---- S = Q @ K^T, 8x8 fragment ----
        float S[8][8];
        #pragma unroll
        for (int i = 0; i < 8; ++i)
            #pragma unroll
            for (int j = 0; j < 8; ++j) S[i][j] = 0.f;

        #pragma unroll 2
        for (int e0 = 0; e0 < 64; e0 += 4) {
            float4 q4[8], k4[8];
            #pragma unroll
            for (int i = 0; i < 8; ++i)
                q4[i] = *reinterpret_cast<const float4*>(&Qs[(ty * 8 + i) * 64 + e0]);
            #pragma unroll
            for (int j = 0; j < 8; ++j)
                k4[j] = *reinterpret_cast<const float4*>(&Ks[(tx * 8 + j) * 64 + (e0 ^ kswz)]);
            #pragma unroll
            for (int i = 0; i < 8; ++i)
                #pragma unroll
                for (int j = 0; j < 8; ++j) {
                    S[i][j] += q4[i].x * k4[j].x;
                    S[i][j] += q4[i].y * k4[j].y;
                    S[i][j] += q4[i].z * k4[j].z;
                    S[i][j] += q4[i].w * k4[j].w;
                }
        }

        // ---- online softmax per row (16 tx lanes own a row) ----
        #pragma unroll
        for (int i = 0; i < 8; ++i) {
            int r = ty * 8 + i;
            float rmax = S[i][0];
            #pragma unroll
            for (int j = 1; j < 8; ++j) rmax = fmaxf(rmax, S[i][j]);
            #pragma unroll
            for (int off = 8; off; off >>= 1)
                rmax = fmaxf(rmax, __shfl_xor_sync(0xffffffffu, rmax, off));

            float old_m = row_m[r];
            float mn = fmaxf(old_m, scale * rmax);
            float rsum = 0.f;
            #pragma unroll
            for (int j = 0; j < 8; ++j) {
                float p = __expf(fmaf(scale, S[i][j], -mn));
                S[i][j] = p;
                rsum += p;
            }
            #pragma unroll
            for (int off = 8; off; off >>= 1)
                rsum += __shfl_xor_sync(0xffffffffu, rsum, off);

            if (tx == 0) {
                float alpha = __expf(old_m - mn);
                row_m[r] = mn;
                row_alpha[r] = alpha;
                row_l[r] = row_l[r] * alpha + rsum;
            }
            // store P row fragment (2 x float4)
            float4 p0 = make_float4(S[i][0], S[i][1], S[i][2], S[i][3]);
            float4 p1 = make_float4(S[i][4], S[i][5], S[i][6], S[i][7]);
            *reinterpret_cast<float4*>(&Ps[r * PP + tx * 8])     = p0;
            *reinterpret_cast<float4*>(&Ps[r * PP + tx * 8 + 4]) = p1;
        }
        __syncthreads();

        // ---- O = O*alpha + P @ V (PV mapping: 4 rows x 8 cols) ----
        #pragma unroll
        for (int i = 0; i < 4; ++i) {
            float a = row_alpha[ry * 4 + i];
            #pragma unroll
            for (int j = 0; j < 8; ++j) O[i][j] *= a;
        }

        #pragma unroll 2
        for (int mi = 0; mi < KTILE; mi += 4) {
            float4 p4[4];
            #pragma unroll
            for (int i = 0; i < 4; ++i)
                p4[i] = *reinterpret_cast<const float4*>(&Ps[(ry * 4 + i) * PP + mi]);
            float4 v4[4][2];
            #pragma unroll
            for (int mm = 0; mm < 4; ++mm) {
                v4[mm][0] = *reinterpret_cast<const float4*>(&Vs[(mi + mm) * 64 + re * 8]);
                v4[mm][1] = *reinterpret_cast<const float4*>(&Vs[(mi + mm) * 64 + re * 8 + 4]);
            }
            #pragma unroll
            for (int i = 0; i < 4; ++i) {
                const float pm[4] = {p4[i].x, p4[i].y, p4[i].z, p4[i].w};
                #pragma unroll
                for (int mm = 0; mm < 4; ++mm) {
                    O[i][0] += pm[mm] * v4[mm][0].x;
                    O[i][1] += pm[mm] * v4[mm][0].y;
                    O[i][2] += pm[mm] * v4[mm][0].z;
                    O[i][3] += pm[mm] * v4[mm][0].w;
                    O[i][4] += pm[mm] * v4[mm][1].x;
                    O[i][5] += pm[mm] * v4[mm][1].y;
                    O[i][6] += pm[mm] * v4[mm][1].z;
                    O[i][7] += pm[mm] * v4[mm][1].w;
                }
            }
        }
    }

    // ---- finalize, write g_o, instance-norm partials ----
    float lsum = 0.f, lsq = 0.f;
    float* Og = g_o + (size_t)s * LSEQ * EDIM + (size_t)row0 * EDIM;
    #pragma unroll
    for (int i = 0; i < 4; ++i) {
        float inv = 1.f / row_l[ry * 4 + i];
        float4 r0, r1;
        float o0 = O[i][0] * inv, o1 = O[i][1] * inv, o2 = O[i][2] * inv, o3 = O[i][3] * inv;
        float o4 = O[i][4] * inv, o5 = O[i][5] * inv, o6 = O[i][6] * inv, o7 = O[i][7] * inv;
        r0 = make_float4(o0, o1, o2, o3);
        r1 = make_float4(o4, o5, o6, o7);
        *reinterpret_cast<float4*>(&Og[(size_t)(ry * 4 + i) * EDIM + re * 8])     = r0;
        *reinterpret_cast<float4*>(&Og[(size_t)(ry * 4 + i) * EDIM + re * 8 + 4]) = r1;
        lsum += o0 + o1 + o2 + o3 + o4 + o5 + o6 + o7;
        lsq  += o0*o0 + o1*o1 + o2*o2 + o3*o3 + o4*o4 + o5*o5 + o6*o6 + o7*o7;
    }

    __syncthreads();                 // all Ps reads done; reuse as reduction scratch
    float* red  = Ps;
    float* red2 = Ps + 256;
    red[tid]  = lsum;
    red2[tid] = lsq;
    __syncthreads();
    #pragma unroll
    for (int st = 128; st; st >>= 1) {
        if (tid < st) { red[tid] += red[tid + st]; red2[tid] += red2[tid + st]; }
        __syncthreads();
    }
    if (tid == 0) g_part[s * NQT + blockIdx.x] = make_float2(red[0], red2[0]);
}

// ----------------------------------------------------------------------------
__global__ void stats_kernel()
{
    const int s = blockIdx.x;
    const int t = threadIdx.x;
    float sum = 0.f, sq = 0.f;
    if (t < NQT) {
        float2 p = g_part[s * NQT + t];
        sum = p.x; sq = p.y;
    }
    #pragma unroll
    for (int off = 16; off; off >>= 1) {
        sum += __shfl_xor_sync(0xffffffffu, sum, off);
        sq  += __shfl_xor_sync(0xffffffffu, sq,  off);
    }
    if (t == 0) {
        const float n = (float)(LSEQ * EDIM);
        float mu  = sum / n;
        float var = sq / n - mu * mu;
        g_stats[s] = make_float2(mu, rsqrtf(var + EPS));
    }
}

__global__ void norm_kernel(float* __restrict__ out)
{
    int idx4 = blockIdx.x * 256 + threadIdx.x;
    int base = idx4 * 4;
    int s = base / (LSEQ * EDIM);
    float2 st = g_stats[s];
    const float4 o = *reinterpret_cast<const float4*>(&g_o[base]);
    float4 r;
    r.x = (o.x - st.x) * st.y;
    r.y = (o.y - st.x) * st.y;
    r.z = (o.z - st.x) * st.y;
    r.w = (o.w - st.x) * st.y;
    *reinterpret_cast<float4*>(&out[base]) = r;
}

// ----------------------------------------------------------------------------
extern "C" void kernel_launch(void* const* d_in, const int* in_sizes, int n_in,
                              void* d_out, int out_size)
{
    const float* info = (const float*)d_in[0];
    const float* Wq   = (const float*)d_in[1];
    const float* bq   = (const float*)d_in[2];
    const float* Wk   = (const float*)d_in[3];
    const float* bk   = (const float*)d_in[4];
    const float* Wv   = (const float*)d_in[5];
    const float* bv   = (const float*)d_in[6];
    float* out = (float*)d_out;

    const int attn_smem = (128 * 64 * 3 + 128 * PP + 3 * 128) * (int)sizeof(float); // 167424
    cudaFuncSetAttribute(attn_kernel,
                         cudaFuncAttributeMaxDynamicSharedMemorySize, attn_smem);

    dim3 pgrid(LSEQ / 128, NSLICE);
    proj_fused_kernel<<<pgrid, 256>>>(info, Wq, bq, Wk, bk, Wv, bv);

    dim3 agrid(NQT, NSLICE);
    attn_kernel<<<agrid, 256, attn_smem>>>();

    stats_kernel<<<NSLICE, 32>>>();

    int total4 = NSLICE * LSEQ * EDIM / 4;
    norm_kernel<<<total4 / 256, 256>>>(out);
}

// round 6
// speedup vs baseline: 1.6476x; 1.6476x over previous
#include <cuda_runtime.h>
#include <cuda_bf16.h>
#include <math.h>
#include <stdint.h>

#define NSLICE 16
#define LSEQ   2048
#define DLLM   768
#define EDIM   64
#define EPS    1e-5f
#define NQT    16

// ---------------- device scratch ----------------
__device__ float g_q[NSLICE*LSEQ*EDIM];
__device__ float g_k[NSLICE*LSEQ*EDIM];
__device__ float g_v[NSLICE*LSEQ*EDIM];
__device__ float g_o[NSLICE*LSEQ*EDIM];
__device__ __nv_bfloat16 g_qh[NSLICE*LSEQ*EDIM];
__device__ __nv_bfloat16 g_ql[NSLICE*LSEQ*EDIM];
__device__ __nv_bfloat16 g_kh[NSLICE*LSEQ*EDIM];
__device__ __nv_bfloat16 g_kl[NSLICE*LSEQ*EDIM];
__device__ __nv_bfloat16 g_vth[NSLICE*EDIM*LSEQ];   // V^T [s][e][key]
__device__ __nv_bfloat16 g_vtl[NSLICE*EDIM*LSEQ];
__device__ float2 g_part[NSLICE*NQT];
__device__ float2 g_stats[NSLICE];

// ---------------- helpers ----------------
__device__ __forceinline__ uint32_t smem_u32(const void* p) {
    uint32_t a;
    asm("{ .reg .u64 t; cvta.to.shared.u64 t, %1; cvt.u32.u64 %0, t; }" : "=r"(a) : "l"(p));
    return a;
}
__device__ __forceinline__ void ldsm4(uint32_t* r, uint32_t addr) {
    asm volatile("ldmatrix.sync.aligned.m8n8.x4.shared.b16 {%0,%1,%2,%3}, [%4];"
                 : "=r"(r[0]), "=r"(r[1]), "=r"(r[2]), "=r"(r[3]) : "r"(addr) : "memory");
}
// canonical x4 addressing: rows row0+(lane%16), k-segment 16B selected by lane/16
__device__ __forceinline__ uint32_t ldsm_addr(uint32_t base, int row0, int kbyte,
                                              int pitch, int lane) {
    return base + (row0 + (lane & 15)) * pitch + kbyte + (lane >> 4) * 16;
}
__device__ __forceinline__ void mma_bf16(float* d, const uint32_t* a,
                                         uint32_t b0, uint32_t b1) {
    asm volatile("mma.sync.aligned.m16n8k16.row.col.f32.bf16.bf16.f32 "
        "{%0,%1,%2,%3}, {%4,%5,%6,%7}, {%8,%9}, {%0,%1,%2,%3};"
        : "+f"(d[0]), "+f"(d[1]), "+f"(d[2]), "+f"(d[3])
        : "r"(a[0]), "r"(a[1]), "r"(a[2]), "r"(a[3]), "r"(b0), "r"(b1));
}
__device__ __forceinline__ void split2(float x0, float x1, uint32_t& h2, uint32_t& l2) {
    __nv_bfloat162 hb = __float22bfloat162_rn(make_float2(x0, x1));
    float2 hf = __bfloat1622float2(hb);
    __nv_bfloat162 lb = __float22bfloat162_rn(make_float2(x0 - hf.x, x1 - hf.y));
    h2 = *reinterpret_cast<uint32_t*>(&hb);
    l2 = *reinterpret_cast<uint32_t*>(&lb);
}

// ----------------------------------------------------------------------------
// Kernel 1 (VERIFIED round-2): fused fp32 projection q,k,v = X @ W + b
// ----------------------------------------------------------------------------
__global__ __launch_bounds__(256, 1)
void proj_fused_kernel(const float* __restrict__ X,
                       const float* __restrict__ Wq, const float* __restrict__ bq,
                       const float* __restrict__ Wk, const float* __restrict__ bk,
                       const float* __restrict__ Wv, const float* __restrict__ bv)
{
    __shared__ float As[128 * 33];
    __shared__ float Bs[3 * 32 * 64];

    const int s    = blockIdx.y;
    const int row0 = blockIdx.x * 128;
    const int tx = threadIdx.x & 15;
    const int ty = threadIdx.x >> 4;
    const int tid = threadIdx.x;

    const float* Xs = X + (size_t)s * LSEQ * DLLM + (size_t)row0 * DLLM;
    const float* Wp[3] = {Wq, Wk, Wv};

    float acc[3][8][4];
    #pragma unroll
    for (int w = 0; w < 3; ++w)
        #pragma unroll
        for (int i = 0; i < 8; ++i)
            #pragma unroll
            for (int j = 0; j < 4; ++j) acc[w][i][j] = 0.f;

    for (int k0 = 0; k0 < DLLM; k0 += 32) {
        #pragma unroll
        for (int t = 0; t < 4; ++t) {
            int f = tid + t * 256;
            int r  = f >> 3;
            int kc = (f & 7) * 4;
            float4 v4 = *reinterpret_cast<const float4*>(&Xs[(size_t)r * DLLM + k0 + kc]);
            float* dst = &As[r * 33 + kc];
            dst[0] = v4.x; dst[1] = v4.y; dst[2] = v4.z; dst[3] = v4.w;
        }
        #pragma unroll
        for (int t = 0; t < 6; ++t) {
            int f = tid + t * 256;
            int w   = f >> 9;
            int rem = f & 511;
            int kk  = rem >> 4;
            int c   = (rem & 15) * 4;
            *reinterpret_cast<float4*>(&Bs[w * 2048 + kk * 64 + c]) =
                *reinterpret_cast<const float4*>(&Wp[w][(size_t)(k0 + kk) * EDIM + c]);
        }
        __syncthreads();

        #pragma unroll 4
        for (int kk = 0; kk < 32; ++kk) {
            float a[8];
            #pragma unroll
            for (int i = 0; i < 8; ++i) a[i] = As[(ty * 8 + i) * 33 + kk];
            #pragma unroll
            for (int w = 0; w < 3; ++w) {
                float4 b4 = *reinterpret_cast<const float4*>(&Bs[w * 2048 + kk * 64 + tx * 4]);
                #pragma unroll
                for (int i = 0; i < 8; ++i) {
                    acc[w][i][0] += a[i] * b4.x;
                    acc[w][i][1] += a[i] * b4.y;
                    acc[w][i][2] += a[i] * b4.z;
                    acc[w][i][3] += a[i] * b4.w;
                }
            }
        }
        __syncthreads();
    }

    const float* bp[3] = {bq, bk, bv};
    float* Yp[3] = {g_q, g_k, g_v};
    #pragma unroll
    for (int w = 0; w < 3; ++w) {
        float4 bb = *reinterpret_cast<const float4*>(&bp[w][tx * 4]);
        float* Ys = Yp[w] + (size_t)s * LSEQ * EDIM + (size_t)row0 * EDIM;
        #pragma unroll
        for (int i = 0; i < 8; ++i) {
            float4 r4;
            r4.x = acc[w][i][0] + bb.x;
            r4.y = acc[w][i][1] + bb.y;
            r4.z = acc[w][i][2] + bb.z;
            r4.w = acc[w][i][3] + bb.w;
            *reinterpret_cast<float4*>(&Ys[(size_t)(ty * 8 + i) * EDIM + tx * 4]) = r4;
        }
    }
}

// ----------------------------------------------------------------------------
// Kernel 2: elementwise bf16 hi/lo split (+ V transpose)
// ----------------------------------------------------------------------------
__global__ void split_kernel()
{
    int idx = blockIdx.x * 256 + threadIdx.x;   // < NSLICE*LSEQ*EDIM
    float q = g_q[idx], k = g_k[idx], v = g_v[idx];

    __nv_bfloat16 qh = __float2bfloat16(q);
    g_qh[idx] = qh;
    g_ql[idx] = __float2bfloat16(q - __bfloat162float(qh));

    __nv_bfloat16 kh = __float2bfloat16(k);
    g_kh[idx] = kh;
    g_kl[idx] = __float2bfloat16(k - __bfloat162float(kh));

    int s = idx / (LSEQ * EDIM);
    int rem = idx % (LSEQ * EDIM);
    int l = rem / EDIM, e = rem % EDIM;
    __nv_bfloat16 vh = __float2bfloat16(v);
    size_t o = ((size_t)s * EDIM + e) * LSEQ + l;
    g_vth[o] = vh;
    g_vtl[o] = __float2bfloat16(v - __bfloat162float(vh));
}

// ----------------------------------------------------------------------------
// Kernel 3: flash attention via mma.sync.m16n8k16 (bf16 hi/lo).
// CTA = 128 q-rows, 8 warps x 16 rows. P goes through SMEM via ldmatrix.
// ----------------------------------------------------------------------------
#define AT_QH   0            /* 128 x 144 */
#define AT_QL   18432
#define AT_KH   36864
#define AT_KL   55296
#define AT_VH   73728        /* 64 x 272 (V^T) */
#define AT_VL   91136
#define AT_PH   108544       /* 128 x 272 */
#define AT_PL   143360
#define AT_RED  178176
#define AT_RED2 179200
#define AT_SMEM 180224

__global__ __launch_bounds__(256, 1)
void attn_kernel()
{
    extern __shared__ char smem[];
    const uint32_t sb = smem_u32(smem);
    const int tid = threadIdx.x, wid = tid >> 5, lane = tid & 31;
    const int g = lane >> 2, tig = lane & 3;
    const int s = blockIdx.y, row0 = blockIdx.x * 128;

    const __nv_bfloat16* Qh = g_qh + (size_t)s * LSEQ * EDIM + (size_t)row0 * EDIM;
    const __nv_bfloat16* Ql = g_ql + (size_t)s * LSEQ * EDIM + (size_t)row0 * EDIM;
    const __nv_bfloat16* Kh = g_kh + (size_t)s * LSEQ * EDIM;
    const __nv_bfloat16* Kl = g_kl + (size_t)s * LSEQ * EDIM;

    // Q tiles hi/lo (2048 uint4, 8/thread)
    #pragma unroll
    for (int t = 0; t < 8; ++t) {
        int f = tid + t * 256;
        int sp = f >> 10, ff = f & 1023;
        int rr = ff >> 3, c8 = (ff & 7) * 8;
        const __nv_bfloat16* src = (sp ? Ql : Qh) + (size_t)rr * EDIM + c8;
        *reinterpret_cast<uint4*>(smem + (sp ? AT_QL : AT_QH) + rr * 144 + c8 * 2) =
            *reinterpret_cast<const uint4*>(src);
    }

    float O[8][4];
    #pragma unroll
    for (int j = 0; j < 8; ++j)
        #pragma unroll
        for (int q = 0; q < 4; ++q) O[j][q] = 0.f;
    float m0 = -1e30f, m1 = -1e30f, l0 = 0.f, l1 = 0.f;
    const float sc = 0.125f;
    const int prow0 = wid * 16 + g;       // this lane's S/P row (and prow0+8)

    for (int kt = 0; kt < LSEQ / 128; ++kt) {
        __syncthreads();
        // K tiles hi/lo
        #pragma unroll
        for (int t = 0; t < 8; ++t) {
            int f = tid + t * 256;
            int sp = f >> 10, ff = f & 1023;
            int rr = ff >> 3, c8 = (ff & 7) * 8;
            const __nv_bfloat16* src = (sp ? Kl : Kh)
                + (size_t)(kt * 128 + rr) * EDIM + c8;
            *reinterpret_cast<uint4*>(smem + (sp ? AT_KL : AT_KH) + rr * 144 + c8 * 2) =
                *reinterpret_cast<const uint4*>(src);
        }
        // V^T tiles hi/lo: 64 e-rows x 128 keys
        #pragma unroll
        for (int t = 0; t < 8; ++t) {
            int f = tid + t * 256;
            int sp = f >> 10, ff = f & 1023;
            int e = ff >> 4, k8 = (ff & 15) * 8;
            const __nv_bfloat16* src = (sp ? g_vtl : g_vth)
                + ((size_t)s * EDIM + e) * LSEQ + kt * 128 + k8;
            *reinterpret_cast<uint4*>(smem + (sp ? AT_VL : AT_VH) + e * 272 + k8 * 2) =
                *reinterpret_cast<const uint4*>(src);
        }
        __syncthreads();

        // ---- S(16 x 128) = Qh Kh^T + Qh Kl^T + Ql Kh^T ----
        float S[16][4];
        #pragma unroll
        for (int nt = 0; nt < 16; ++nt)
            #pragma unroll
            for (int q = 0; q < 4; ++q) S[nt][q] = 0.f;

        #pragma unroll
        for (int kb = 0; kb < 4; ++kb) {
            const int kby = kb * 32;
            uint32_t aH[4], aL[4];
            ldsm4(aH, ldsm_addr(sb + AT_QH, wid * 16, kby, 144, lane));
            ldsm4(aL, ldsm_addr(sb + AT_QL, wid * 16, kby, 144, lane));
            #pragma unroll
            for (int ntp = 0; ntp < 8; ++ntp) {
                uint32_t bh[4], bl[4];
                ldsm4(bh, ldsm_addr(sb + AT_KH, ntp * 16, kby, 144, lane));
                ldsm4(bl, ldsm_addr(sb + AT_KL, ntp * 16, kby, 144, lane));
                mma_bf16(S[2*ntp],   aH, bh[0], bh[2]);
                mma_bf16(S[2*ntp+1], aH, bh[1], bh[3]);
                mma_bf16(S[2*ntp],   aH, bl[0], bl[2]);
                mma_bf16(S[2*ntp+1], aH, bl[1], bl[3]);
                mma_bf16(S[2*ntp],   aL, bh[0], bh[2]);
                mma_bf16(S[2*ntp+1], aL, bh[1], bh[3]);
            }
        }

        // ---- online softmax (rows prow0, prow0+8; quad t holds col pairs) ----
        float mx0 = -1e30f, mx1 = -1e30f;
        #pragma unroll
        for (int nt = 0; nt < 16; ++nt) {
            mx0 = fmaxf(mx0, fmaxf(S[nt][0], S[nt][1]));
            mx1 = fmaxf(mx1, fmaxf(S[nt][2], S[nt][3]));
        }
        mx0 = fmaxf(mx0, __shfl_xor_sync(0xffffffffu, mx0, 1));
        mx0 = fmaxf(mx0, __shfl_xor_sync(0xffffffffu, mx0, 2));
        mx1 = fmaxf(mx1, __shfl_xor_sync(0xffffffffu, mx1, 1));
        mx1 = fmaxf(mx1, __shfl_xor_sync(0xffffffffu, mx1, 2));
        float mn0 = fmaxf(m0, sc * mx0), mn1 = fmaxf(m1, sc * mx1);
        float a0 = __expf(m0 - mn0), a1 = __expf(m1 - mn1);
        m0 = mn0; m1 = mn1;
        float s0 = 0.f, s1 = 0.f;
        #pragma unroll
        for (int nt = 0; nt < 16; ++nt) {
            S[nt][0] = __expf(fmaf(sc, S[nt][0], -mn0));
            S[nt][1] = __expf(fmaf(sc, S[nt][1], -mn0));
            S[nt][2] = __expf(fmaf(sc, S[nt][2], -mn1));
            S[nt][3] = __expf(fmaf(sc, S[nt][3], -mn1));
            s0 += S[nt][0] + S[nt][1];
            s1 += S[nt][2] + S[nt][3];
        }
        s0 += __shfl_xor_sync(0xffffffffu, s0, 1);
        s0 += __shfl_xor_sync(0xffffffffu, s0, 2);
        s1 += __shfl_xor_sync(0xffffffffu, s1, 1);
        s1 += __shfl_xor_sync(0xffffffffu, s1, 2);
        l0 = l0 * a0 + s0;
        l1 = l1 * a1 + s1;

        // ---- P -> SMEM (hi/lo), rows prow0 / prow0+8, keys nt*8 + 2*tig ----
        #pragma unroll
        for (int nt = 0; nt < 16; ++nt) {
            uint32_t h01, l01, h23, l23;
            split2(S[nt][0], S[nt][1], h01, l01);
            split2(S[nt][2], S[nt][3], h23, l23);
            int kbyte = (nt * 8 + tig * 2) * 2;
            *reinterpret_cast<uint32_t*>(smem + AT_PH + prow0 * 272 + kbyte)       = h01;
            *reinterpret_cast<uint32_t*>(smem + AT_PL + prow0 * 272 + kbyte)       = l01;
            *reinterpret_cast<uint32_t*>(smem + AT_PH + (prow0 + 8) * 272 + kbyte) = h23;
            *reinterpret_cast<uint32_t*>(smem + AT_PL + (prow0 + 8) * 272 + kbyte) = l23;
        }
        __syncwarp();    // P rows are warp-private; warp-level visibility suffices

        // rescale O
        #pragma unroll
        for (int j = 0; j < 8; ++j) {
            O[j][0] *= a0; O[j][1] *= a0;
            O[j][2] *= a1; O[j][3] *= a1;
        }

        // ---- O += Ph Vh^T + Ph Vl^T + Pl Vh^T ----
        #pragma unroll
        for (int kb = 0; kb < 8; ++kb) {
            const int kby = kb * 32;
            uint32_t pH[4], pL[4];
            ldsm4(pH, ldsm_addr(sb + AT_PH, wid * 16, kby, 272, lane));
            ldsm4(pL, ldsm_addr(sb + AT_PL, wid * 16, kby, 272, lane));
            #pragma unroll
            for (int ntp = 0; ntp < 4; ++ntp) {
                uint32_t vh[4], vl[4];
                ldsm4(vh, ldsm_addr(sb + AT_VH, ntp * 16, kby, 272, lane));
                ldsm4(vl, ldsm_addr(sb + AT_VL, ntp * 16, kby, 272, lane));
                mma_bf16(O[2*ntp],   pH, vh[0], vh[2]);
                mma_bf16(O[2*ntp+1], pH, vh[1], vh[3]);
                mma_bf16(O[2*ntp],   pH, vl[0], vl[2]);
                mma_bf16(O[2*ntp+1], pH, vl[1], vl[3]);
                mma_bf16(O[2*ntp],   pL, vh[0], vh[2]);
                mma_bf16(O[2*ntp+1], pL, vh[1], vh[3]);
            }
        }
    }

    // ---- finalize: /l, write g_o, instance-norm partials ----
    const float inv0 = 1.f / l0, inv1 = 1.f / l1;
    const int r0 = row0 + prow0, r1 = r0 + 8;
    float* Og = g_o + (size_t)s * LSEQ * EDIM;
    float lsum = 0.f, lsq = 0.f;
    #pragma unroll
    for (int j = 0; j < 8; ++j) {
        int c = tig * 2 + 8 * j;
        float o00 = O[j][0] * inv0, o01 = O[j][1] * inv0;
        float o10 = O[j][2] * inv1, o11 = O[j][3] * inv1;
        *reinterpret_cast<float2*>(Og + (size_t)r0 * EDIM + c) = make_float2(o00, o01);
        *reinterpret_cast<float2*>(Og + (size_t)r1 * EDIM + c) = make_float2(o10, o11);
        lsum += o00 + o01 + o10 + o11;
        lsq  += o00*o00 + o01*o01 + o10*o10 + o11*o11;
    }

    float* red  = reinterpret_cast<float*>(smem + AT_RED);
    float* red2 = reinterpret_cast<float*>(smem + AT_RED2);
    __syncthreads();
    red[tid] = lsum; red2[tid] = lsq;
    __syncthreads();
    #pragma unroll
    for (int st = 128; st; st >>= 1) {
        if (tid < st) { red[tid] += red[tid + st]; red2[tid] += red2[tid + st]; }
        __syncthreads();
    }
    if (tid == 0) g_part[s * NQT + blockIdx.x] = make_float2(red[0], red2[0]);
}

// ---------------- kernels 4/5: stats + normalize ----------------
__global__ void stats_kernel()
{
    const int s = blockIdx.x, t = threadIdx.x;
    float sum = 0.f, sq = 0.f;
    if (t < NQT) { float2 p = g_part[s * NQT + t]; sum = p.x; sq = p.y; }
    #pragma unroll
    for (int off = 16; off; off >>= 1) {
        sum += __shfl_xor_sync(0xffffffffu, sum, off);
        sq  += __shfl_xor_sync(0xffffffffu, sq,  off);
    }
    if (t == 0) {
        const float n = (float)(LSEQ * EDIM);
        float mu = sum / n;
        float var = sq / n - mu * mu;
        g_stats[s] = make_float2(mu, rsqrtf(var + EPS));
    }
}

__global__ void norm_kernel(float* __restrict__ out)
{
    int base = (blockIdx.x * 256 + threadIdx.x) * 4;
    int s = base / (LSEQ * EDIM);
    float2 st = g_stats[s];
    const float4 o = *reinterpret_cast<const float4*>(&g_o[base]);
    float4 rr;
    rr.x = (o.x - st.x) * st.y; rr.y = (o.y - st.x) * st.y;
    rr.z = (o.z - st.x) * st.y; rr.w = (o.w - st.x) * st.y;
    *reinterpret_cast<float4*>(&out[base]) = rr;
}

// ---------------- host ----------------
extern "C" void kernel_launch(void* const* d_in, const int* in_sizes, int n_in,
                              void* d_out, int out_size)
{
    const float* info = (const float*)d_in[0];
    const float* Wq = (const float*)d_in[1];
    const float* bq = (const float*)d_in[2];
    const float* Wk = (const float*)d_in[3];
    const float* bk = (const float*)d_in[4];
    const float* Wv = (const float*)d_in[5];
    const float* bv = (const float*)d_in[6];
    float* out = (float*)d_out;

    cudaFuncSetAttribute(attn_kernel, cudaFuncAttributeMaxDynamicSharedMemorySize, AT_SMEM);

    proj_fused_kernel<<<dim3(LSEQ / 128, NSLICE), 256>>>(info, Wq, bq, Wk, bk, Wv, bv);
    split_kernel<<<NSLICE * LSEQ * EDIM / 256, 256>>>();
    attn_kernel<<<dim3(NQT, NSLICE), 256, AT_SMEM>>>();
    stats_kernel<<<NSLICE, 32>>>();
    norm_kernel<<<NSLICE * LSEQ * EDIM / 1024, 256>>>(out);
}

// round 7
// speedup vs baseline: 2.6423x; 1.6037x over previous
#include <cuda_runtime.h>
#include <cuda_bf16.h>
#include <math.h>
#include <stdint.h>

#define NSLICE 16
#define LSEQ   2048
#define DLLM   768
#define EDIM   64
#define EPS    1e-5f
#define NQT    16

// ---------------- device scratch ----------------
__device__ float g_o[NSLICE*LSEQ*EDIM];
__device__ __nv_bfloat16 g_qh[NSLICE*LSEQ*EDIM];
__device__ __nv_bfloat16 g_ql[NSLICE*LSEQ*EDIM];
__device__ __nv_bfloat16 g_kh[NSLICE*LSEQ*EDIM];
__device__ __nv_bfloat16 g_kl[NSLICE*LSEQ*EDIM];
__device__ __nv_bfloat16 g_vth[NSLICE*EDIM*LSEQ];   // V^T [s][e][key]
__device__ __nv_bfloat16 g_vtl[NSLICE*EDIM*LSEQ];
__device__ __nv_bfloat16 g_wth[3*EDIM*DLLM];        // W^T [w][n][k] hi
__device__ __nv_bfloat16 g_wtl[3*EDIM*DLLM];        // lo
__device__ float2 g_part[NSLICE*NQT];
__device__ float2 g_stats[NSLICE];

// ---------------- helpers (all validated in round 6) ----------------
__device__ __forceinline__ uint32_t smem_u32(const void* p) {
    uint32_t a;
    asm("{ .reg .u64 t; cvta.to.shared.u64 t, %1; cvt.u32.u64 %0, t; }" : "=r"(a) : "l"(p));
    return a;
}
__device__ __forceinline__ void ldsm4(uint32_t* r, uint32_t addr) {
    asm volatile("ldmatrix.sync.aligned.m8n8.x4.shared.b16 {%0,%1,%2,%3}, [%4];"
                 : "=r"(r[0]), "=r"(r[1]), "=r"(r[2]), "=r"(r[3]) : "r"(addr) : "memory");
}
__device__ __forceinline__ uint32_t ldsm_addr(uint32_t base, int row0, int kbyte,
                                              int pitch, int lane) {
    return base + (row0 + (lane & 15)) * pitch + kbyte + (lane >> 4) * 16;
}
__device__ __forceinline__ void mma_bf16(float* d, const uint32_t* a,
                                         uint32_t b0, uint32_t b1) {
    asm volatile("mma.sync.aligned.m16n8k16.row.col.f32.bf16.bf16.f32 "
        "{%0,%1,%2,%3}, {%4,%5,%6,%7}, {%8,%9}, {%0,%1,%2,%3};"
        : "+f"(d[0]), "+f"(d[1]), "+f"(d[2]), "+f"(d[3])
        : "r"(a[0]), "r"(a[1]), "r"(a[2]), "r"(a[3]), "r"(b0), "r"(b1));
}
__device__ __forceinline__ void split2(float x0, float x1, uint32_t& h2, uint32_t& l2) {
    __nv_bfloat162 hb = __float22bfloat162_rn(make_float2(x0, x1));
    float2 hf = __bfloat1622float2(hb);
    __nv_bfloat162 lb = __float22bfloat162_rn(make_float2(x0 - hf.x, x1 - hf.y));
    h2 = *reinterpret_cast<uint32_t*>(&hb);
    l2 = *reinterpret_cast<uint32_t*>(&lb);
}

// ---------------- kernel 0: W^T hi/lo split ----------------
__global__ void wsplit_kernel(const float* __restrict__ Wq,
                              const float* __restrict__ Wk,
                              const float* __restrict__ Wv) {
    int idx = blockIdx.x * 256 + threadIdx.x;
    if (idx >= 3 * EDIM * DLLM) return;
    int w = idx / (EDIM * DLLM), rem = idx % (EDIM * DLLM);
    int n = rem / DLLM, k = rem % DLLM;
    const float* W = (w == 0) ? Wq : (w == 1) ? Wk : Wv;
    float x = W[k * EDIM + n];
    __nv_bfloat16 h = __float2bfloat16(x);
    g_wth[idx] = h;
    g_wtl[idx] = __float2bfloat16(x - __bfloat162float(h));
}

// ----------------------------------------------------------------------------
// Kernel 1: projections via mma.sync (hi/lo bf16), fused output split.
// CTA = 128 rows x (q|k|v n=64 each); K chunked by 64; 8 warps x 16 rows.
// ----------------------------------------------------------------------------
#define PR_AH 0            /* 128 x 144 */
#define PR_AL 18432
#define PR_B  36864        /* 6 x (64 x 144) */
#define PR_SMEM 92160

__global__ __launch_bounds__(256, 1)
void proj_kernel(const float* __restrict__ X, const float* __restrict__ bq,
                 const float* __restrict__ bk, const float* __restrict__ bv)
{
    extern __shared__ char smem[];
    const uint32_t sb = smem_u32(smem);
    const int tid = threadIdx.x, wid = tid >> 5, lane = tid & 31;
    const int g = lane >> 2, tig = lane & 3;
    const int s = blockIdx.y, row0 = blockIdx.x * 128;
    const float* Xs = X + (size_t)s * LSEQ * DLLM + (size_t)row0 * DLLM;

    float acc[3][8][4];
    #pragma unroll
    for (int w = 0; w < 3; ++w)
        #pragma unroll
        for (int j = 0; j < 8; ++j)
            #pragma unroll
            for (int q = 0; q < 4; ++q) acc[w][j][q] = 0.f;

    for (int chunk = 0; chunk < 12; ++chunk) {
        const int k0 = chunk * 64;
        __syncthreads();
        // A: 128x64 fp32 -> hi/lo bf16, pitch 144 (2048 float4, 8/thread)
        #pragma unroll
        for (int t = 0; t < 8; ++t) {
            int f = tid + t * 256;
            int r = f >> 4, c4 = (f & 15) * 4;
            float4 x = *reinterpret_cast<const float4*>(&Xs[(size_t)r * DLLM + k0 + c4]);
            uint32_t h0, l0, h1, l1;
            split2(x.x, x.y, h0, l0);
            split2(x.z, x.w, h1, l1);
            *reinterpret_cast<uint2*>(smem + PR_AH + r * 144 + c4 * 2) = make_uint2(h0, h1);
            *reinterpret_cast<uint2*>(smem + PR_AL + r * 144 + c4 * 2) = make_uint2(l0, l1);
        }
        // B: 6 tiles [64n x 64k] bf16, pitch 144 (3072 uint4, 12/thread)
        #pragma unroll
        for (int t = 0; t < 12; ++t) {
            int f = tid + t * 256;
            int iwsp = f >> 9, rem = f & 511;
            int n = rem >> 3, k8 = (rem & 7) * 8;
            int iw = iwsp >> 1, sp = iwsp & 1;
            const __nv_bfloat16* src = (sp ? g_wtl : g_wth)
                + (size_t)iw * EDIM * DLLM + (size_t)n * DLLM + k0 + k8;
            *reinterpret_cast<uint4*>(smem + PR_B + iwsp * 9216 + n * 144 + k8 * 2) =
                *reinterpret_cast<const uint4*>(src);
        }
        __syncthreads();

        #pragma unroll
        for (int kb = 0; kb < 4; ++kb) {
            const int kby = kb * 32;
            uint32_t aH[4], aL[4];
            ldsm4(aH, ldsm_addr(sb + PR_AH, wid * 16, kby, 144, lane));
            ldsm4(aL, ldsm_addr(sb + PR_AL, wid * 16, kby, 144, lane));
            #pragma unroll
            for (int w = 0; w < 3; ++w) {
                const uint32_t bhb = sb + PR_B + (w * 2) * 9216;
                const uint32_t blb = sb + PR_B + (w * 2 + 1) * 9216;
                #pragma unroll
                for (int ntp = 0; ntp < 4; ++ntp) {
                    uint32_t bh[4], bl[4];
                    ldsm4(bh, ldsm_addr(bhb, ntp * 16, kby, 144, lane));
                    ldsm4(bl, ldsm_addr(blb, ntp * 16, kby, 144, lane));
                    mma_bf16(acc[w][2*ntp],   aH, bh[0], bh[2]);
                    mma_bf16(acc[w][2*ntp+1], aH, bh[1], bh[3]);
                    mma_bf16(acc[w][2*ntp],   aH, bl[0], bl[2]);
                    mma_bf16(acc[w][2*ntp+1], aH, bl[1], bl[3]);
                    mma_bf16(acc[w][2*ntp],   aL, bh[0], bh[2]);
                    mma_bf16(acc[w][2*ntp+1], aL, bh[1], bh[3]);
                }
            }
        }
    }

    // epilogue: +bias, split hi/lo, store q/k row-major and v transposed.
    // C-fragment mapping (validated): rows r0 = row0+wid*16+g, r1 = r0+8;
    // cols c = 2*tig + 8*j; acc[.][j] = {(r0,c),(r0,c+1),(r1,c),(r1,c+1)}.
    const int r0 = row0 + wid * 16 + g, r1 = r0 + 8;
    #pragma unroll
    for (int w = 0; w < 3; ++w) {
        const float* bias = (w == 0) ? bq : (w == 1) ? bk : bv;
        #pragma unroll
        for (int j = 0; j < 8; ++j) {
            int c = tig * 2 + 8 * j;
            float b0 = bias[c], b1 = bias[c + 1];
            float v00 = acc[w][j][0] + b0, v01 = acc[w][j][1] + b1;   // row r0
            float v10 = acc[w][j][2] + b0, v11 = acc[w][j][3] + b1;   // row r1
            if (w < 2) {
                __nv_bfloat16* dh = (w ? g_kh : g_qh) + (size_t)s * LSEQ * EDIM;
                __nv_bfloat16* dl = (w ? g_kl : g_ql) + (size_t)s * LSEQ * EDIM;
                uint32_t h0, l0, h1, l1;
                split2(v00, v01, h0, l0);
                split2(v10, v11, h1, l1);
                *reinterpret_cast<uint32_t*>(dh + (size_t)r0 * EDIM + c) = h0;
                *reinterpret_cast<uint32_t*>(dl + (size_t)r0 * EDIM + c) = l0;
                *reinterpret_cast<uint32_t*>(dh + (size_t)r1 * EDIM + c) = h1;
                *reinterpret_cast<uint32_t*>(dl + (size_t)r1 * EDIM + c) = l1;
            } else {
                float vals[4] = {v00, v01, v10, v11};
                #pragma unroll
                for (int q = 0; q < 4; ++q) {
                    int e = c + (q & 1);
                    int key = (q < 2) ? r0 : r1;
                    float v = vals[q];
                    __nv_bfloat16 h = __float2bfloat16(v);
                    size_t o = ((size_t)s * EDIM + e) * LSEQ + key;
                    g_vth[o] = h;
                    g_vtl[o] = __float2bfloat16(v - __bfloat162float(h));
                }
            }
        }
    }
}

// ----------------------------------------------------------------------------
// Kernel 2: flash attention via mma.sync (UNCHANGED from validated round 6)
// ----------------------------------------------------------------------------
#define AT_QH   0
#define AT_QL   18432
#define AT_KH   36864
#define AT_KL   55296
#define AT_VH   73728
#define AT_VL   91136
#define AT_PH   108544
#define AT_PL   143360
#define AT_RED  178176
#define AT_RED2 179200
#define AT_SMEM 180224

__global__ __launch_bounds__(256, 1)
void attn_kernel()
{
    extern __shared__ char smem[];
    const uint32_t sb = smem_u32(smem);
    const int tid = threadIdx.x, wid = tid >> 5, lane = tid & 31;
    const int g = lane >> 2, tig = lane & 3;
    const int s = blockIdx.y, row0 = blockIdx.x * 128;

    const __nv_bfloat16* Qh = g_qh + (size_t)s * LSEQ * EDIM + (size_t)row0 * EDIM;
    const __nv_bfloat16* Ql = g_ql + (size_t)s * LSEQ * EDIM + (size_t)row0 * EDIM;
    const __nv_bfloat16* Kh = g_kh + (size_t)s * LSEQ * EDIM;
    const __nv_bfloat16* Kl = g_kl + (size_t)s * LSEQ * EDIM;

    #pragma unroll
    for (int t = 0; t < 8; ++t) {
        int f = tid + t * 256;
        int sp = f >> 10, ff = f & 1023;
        int rr = ff >> 3, c8 = (ff & 7) * 8;
        const __nv_bfloat16* src = (sp ? Ql : Qh) + (size_t)rr * EDIM + c8;
        *reinterpret_cast<uint4*>(smem + (sp ? AT_QL : AT_QH) + rr * 144 + c8 * 2) =
            *reinterpret_cast<const uint4*>(src);
    }

    float O[8][4];
    #pragma unroll
    for (int j = 0; j < 8; ++j)
        #pragma unroll
        for (int q = 0; q < 4; ++q) O[j][q] = 0.f;
    float m0 = -1e30f, m1 = -1e30f, l0 = 0.f, l1 = 0.f;
    const float sc = 0.125f;
    const int prow0 = wid * 16 + g;

    for (int kt = 0; kt < LSEQ / 128; ++kt) {
        __syncthreads();
        #pragma unroll
        for (int t = 0; t < 8; ++t) {
            int f = tid + t * 256;
            int sp = f >> 10, ff = f & 1023;
            int rr = ff >> 3, c8 = (ff & 7) * 8;
            const __nv_bfloat16* src = (sp ? Kl : Kh)
                + (size_t)(kt * 128 + rr) * EDIM + c8;
            *reinterpret_cast<uint4*>(smem + (sp ? AT_KL : AT_KH) + rr * 144 + c8 * 2) =
                *reinterpret_cast<const uint4*>(src);
        }
        #pragma unroll
        for (int t = 0; t < 8; ++t) {
            int f = tid + t * 256;
            int sp = f >> 10, ff = f & 1023;
            int e = ff >> 4, k8 = (ff & 15) * 8;
            const __nv_bfloat16* src = (sp ? g_vtl : g_vth)
                + ((size_t)s * EDIM + e) * LSEQ + kt * 128 + k8;
            *reinterpret_cast<uint4*>(smem + (sp ? AT_VL : AT_VH) + e * 272 + k8 * 2) =
                *reinterpret_cast<const uint4*>(src);
        }
        __syncthreads();

        float S[16][4];
        #pragma unroll
        for (int nt = 0; nt < 16; ++nt)
            #pragma unroll
            for (int q = 0; q < 4; ++q) S[nt][q] = 0.f;

        #pragma unroll
        for (int kb = 0; kb < 4; ++kb) {
            const int kby = kb * 32;
            uint32_t aH[4], aL[4];
            ldsm4(aH, ldsm_addr(sb + AT_QH, wid * 16, kby, 144, lane));
            ldsm4(aL, ldsm_addr(sb + AT_QL, wid * 16, kby, 144, lane));
            #pragma unroll
            for (int ntp = 0; ntp < 8; ++ntp) {
                uint32_t bh[4], bl[4];
                ldsm4(bh, ldsm_addr(sb + AT_KH, ntp * 16, kby, 144, lane));
                ldsm4(bl, ldsm_addr(sb + AT_KL, ntp * 16, kby, 144, lane));
                mma_bf16(S[2*ntp],   aH, bh[0], bh[2]);
                mma_bf16(S[2*ntp+1], aH, bh[1], bh[3]);
                mma_bf16(S[2*ntp],   aH, bl[0], bl[2]);
                mma_bf16(S[2*ntp+1], aH, bl[1], bl[3]);
                mma_bf16(S[2*ntp],   aL, bh[0], bh[2]);
                mma_bf16(S[2*ntp+1], aL, bh[1], bh[3]);
            }
        }

        float mx0 = -1e30f, mx1 = -1e30f;
        #pragma unroll
        for (int nt = 0; nt < 16; ++nt) {
            mx0 = fmaxf(mx0, fmaxf(S[nt][0], S[nt][1]));
            mx1 = fmaxf(mx1, fmaxf(S[nt][2], S[nt][3]));
        }
        mx0 = fmaxf(mx0, __shfl_xor_sync(0xffffffffu, mx0, 1));
        mx0 = fmaxf(mx0, __shfl_xor_sync(0xffffffffu, mx0, 2));
        mx1 = fmaxf(mx1, __shfl_xor_sync(0xffffffffu, mx1, 1));
        mx1 = fmaxf(mx1, __shfl_xor_sync(0xffffffffu, mx1, 2));
        float mn0 = fmaxf(m0, sc * mx0), mn1 = fmaxf(m1, sc * mx1);
        float a0 = __expf(m0 - mn0), a1 = __expf(m1 - mn1);
        m0 = mn0; m1 = mn1;
        float s0 = 0.f, s1 = 0.f;
        #pragma unroll
        for (int nt = 0; nt < 16; ++nt) {
            S[nt][0] = __expf(fmaf(sc, S[nt][0], -mn0));
            S[nt][1] = __expf(fmaf(sc, S[nt][1], -mn0));
            S[nt][2] = __expf(fmaf(sc, S[nt][2], -mn1));
            S[nt][3] = __expf(fmaf(sc, S[nt][3], -mn1));
            s0 += S[nt][0] + S[nt][1];
            s1 += S[nt][2] + S[nt][3];
        }
        s0 += __shfl_xor_sync(0xffffffffu, s0, 1);
        s0 += __shfl_xor_sync(0xffffffffu, s0, 2);
        s1 += __shfl_xor_sync(0xffffffffu, s1, 1);
        s1 += __shfl_xor_sync(0xffffffffu, s1, 2);
        l0 = l0 * a0 + s0;
        l1 = l1 * a1 + s1;

        #pragma unroll
        for (int nt = 0; nt < 16; ++nt) {
            uint32_t h01, l01, h23, l23;
            split2(S[nt][0], S[nt][1], h01, l01);
            split2(S[nt][2], S[nt][3], h23, l23);
            int kbyte = (nt * 8 + tig * 2) * 2;
            *reinterpret_cast<uint32_t*>(smem + AT_PH + prow0 * 272 + kbyte)       = h01;
            *reinterpret_cast<uint32_t*>(smem + AT_PL + prow0 * 272 + kbyte)       = l01;
            *reinterpret_cast<uint32_t*>(smem + AT_PH + (prow0 + 8) * 272 + kbyte) = h23;
            *reinterpret_cast<uint32_t*>(smem + AT_PL + (prow0 + 8) * 272 + kbyte) = l23;
        }
        __syncwarp();

        #pragma unroll
        for (int j = 0; j < 8; ++j) {
            O[j][0] *= a0; O[j][1] *= a0;
            O[j][2] *= a1; O[j][3] *= a1;
        }

        #pragma unroll
        for (int kb = 0; kb < 8; ++kb) {
            const int kby = kb * 32;
            uint32_t pH[4], pL[4];
            ldsm4(pH, ldsm_addr(sb + AT_PH, wid * 16, kby, 272, lane));
            ldsm4(pL, ldsm_addr(sb + AT_PL, wid * 16, kby, 272, lane));
            #pragma unroll
            for (int ntp = 0; ntp < 4; ++ntp) {
                uint32_t vh[4], vl[4];
                ldsm4(vh, ldsm_addr(sb + AT_VH, ntp * 16, kby, 272, lane));
                ldsm4(vl, ldsm_addr(sb + AT_VL, ntp * 16, kby, 272, lane));
                mma_bf16(O[2*ntp],   pH, vh[0], vh[2]);
                mma_bf16(O[2*ntp+1], pH, vh[1], vh[3]);
                mma_bf16(O[2*ntp],   pH, vl[0], vl[2]);
                mma_bf16(O[2*ntp+1], pH, vl[1], vl[3]);
                mma_bf16(O[2*ntp],   pL, vh[0], vh[2]);
                mma_bf16(O[2*ntp+1], pL, vh[1], vh[3]);
            }
        }
    }

    const float inv0 = 1.f / l0, inv1 = 1.f / l1;
    const int r0 = row0 + prow0, r1 = r0 + 8;
    float* Og = g_o + (size_t)s * LSEQ * EDIM;
    float lsum = 0.f, lsq = 0.f;
    #pragma unroll
    for (int j = 0; j < 8; ++j) {
        int c = tig * 2 + 8 * j;
        float o00 = O[j][0] * inv0, o01 = O[j][1] * inv0;
        float o10 = O[j][2] * inv1, o11 = O[j][3] * inv1;
        *reinterpret_cast<float2*>(Og + (size_t)r0 * EDIM + c) = make_float2(o00, o01);
        *reinterpret_cast<float2*>(Og + (size_t)r1 * EDIM + c) = make_float2(o10, o11);
        lsum += o00 + o01 + o10 + o11;
        lsq  += o00*o00 + o01*o01 + o10*o10 + o11*o11;
    }

    float* red  = reinterpret_cast<float*>(smem + AT_RED);
    float* red2 = reinterpret_cast<float*>(smem + AT_RED2);
    __syncthreads();
    red[tid] = lsum; red2[tid] = lsq;
    __syncthreads();
    #pragma unroll
    for (int st = 128; st; st >>= 1) {
        if (tid < st) { red[tid] += red[tid + st]; red2[tid] += red2[tid + st]; }
        __syncthreads();
    }
    if (tid == 0) g_part[s * NQT + blockIdx.x] = make_float2(red[0], red2[0]);
}

// ---------------- kernels 3/4 ----------------
__global__ void stats_kernel()
{
    const int s = blockIdx.x, t = threadIdx.x;
    float sum = 0.f, sq = 0.f;
    if (t < NQT) { float2 p = g_part[s * NQT + t]; sum = p.x; sq = p.y; }
    #pragma unroll
    for (int off = 16; off; off >>= 1) {
        sum += __shfl_xor_sync(0xffffffffu, sum, off);
        sq  += __shfl_xor_sync(0xffffffffu, sq,  off);
    }
    if (t == 0) {
        const float n = (float)(LSEQ * EDIM);
        float mu = sum / n;
        float var = sq / n - mu * mu;
        g_stats[s] = make_float2(mu, rsqrtf(var + EPS));
    }
}

__global__ void norm_kernel(float* __restrict__ out)
{
    int base = (blockIdx.x * 256 + threadIdx.x) * 4;
    int s = base / (LSEQ * EDIM);
    float2 st = g_stats[s];
    const float4 o = *reinterpret_cast<const float4*>(&g_o[base]);
    float4 rr;
    rr.x = (o.x - st.x) * st.y; rr.y = (o.y - st.x) * st.y;
    rr.z = (o.z - st.x) * st.y; rr.w = (o.w - st.x) * st.y;
    *reinterpret_cast<float4*>(&out[base]) = rr;
}

// ---------------- host ----------------
extern "C" void kernel_launch(void* const* d_in, const int* in_sizes, int n_in,
                              void* d_out, int out_size)
{
    const float* info = (const float*)d_in[0];
    const float* Wq = (const float*)d_in[1];
    const float* bq = (const float*)d_in[2];
    const float* Wk = (const float*)d_in[3];
    const float* bk = (const float*)d_in[4];
    const float* Wv = (const float*)d_in[5];
    const float* bv = (const float*)d_in[6];
    float* out = (float*)d_out;

    cudaFuncSetAttribute(proj_kernel, cudaFuncAttributeMaxDynamicSharedMemorySize, PR_SMEM);
    cudaFuncSetAttribute(attn_kernel, cudaFuncAttributeMaxDynamicSharedMemorySize, AT_SMEM);

    wsplit_kernel<<<(3 * EDIM * DLLM + 255) / 256, 256>>>(Wq, Wk, Wv);
    proj_kernel<<<dim3(LSEQ / 128, NSLICE), 256, PR_SMEM>>>(info, bq, bk, bv);
    attn_kernel<<<dim3(NQT, NSLICE), 256, AT_SMEM>>>();
    stats_kernel<<<NSLICE, 32>>>();
    norm_kernel<<<NSLICE * LSEQ * EDIM / 1024, 256>>>(out);
}